// round 11
// baseline (speedup 1.0000x reference)
#include <cuda_runtime.h>
#include <cuda_bf16.h>
#include <cuda_fp16.h>
#include <math.h>
#include <stdint.h>

#define NN   50000
#define NE   262144
#define NOCP 32768
#define EA   (NE - NOCP)      // 229376
#define NG   64
#define HD   128

// ---------------- scratch ----------------------------------------------------
__device__ float g_S   [NN * HD];
__device__ float g_Mm  [NN * HD];
__device__ float g_aggR[NN * HD];       // sum over edges [NOCP, NE)
__device__ float g_aggO[NN * HD];       // sum over edges [0, NOCP)
__device__ uint32_t g_P16[(size_t)NN * 256];   // P as fp16 pairs
__device__ uint32_t g_Q16[(size_t)NN * 256];   // Q as fp16 pairs
__device__ float g_sel [EA];
__device__ float g_ex  [EA];
__device__ int   g_seg [EA];
__device__ int   g_lbl [EA];
__device__ float g_bc  [128];
__device__ uint32_t g_W2p[256 * 256];   // Wr2 fp16 pairs (kp x 256)
__device__ uint32_t g_Wcp[128 * 128];   // Wc  fp16 pairs (kp x 128)
__device__ uint32_t g_W1p[128 * 512];   // Wr1 fp16 pairs (kp x 512)
__device__ int   g_mx  [NG];
__device__ float g_sum [NG];
__device__ unsigned long long g_pk[NG]; // packed (prob bits << 32) | (EA - e)

// ---------------- helpers -----------------------------------------------------
__device__ __forceinline__ void cvt_pair(float f0, float f1, uint32_t& h, uint32_t& l) {
    __nv_bfloat162 H = __floats2bfloat162_rn(f0, f1);
    float2 Hf = __bfloat1622float2(H);
    __nv_bfloat162 L = __floats2bfloat162_rn(f0 - Hf.x, f1 - Hf.y);
    h = *(uint32_t*)&H;
    l = *(uint32_t*)&L;
}
__device__ __forceinline__ uint32_t cvt_h2(float f0, float f1) {
    __half2 H = __floats2half2_rn(f0, f1);
    return *(uint32_t*)&H;
}
__device__ __forceinline__ void cvt_splith(float f0, float f1, uint32_t& h, uint32_t& l) {
    __half2 H = __floats2half2_rn(f0, f1);
    float2 Hf = __half22float2(H);
    __half2 L = __floats2half2_rn(f0 - Hf.x, f1 - Hf.y);
    h = *(uint32_t*)&H;
    l = *(uint32_t*)&L;
}
__device__ __forceinline__ float2 h2f2(uint32_t u) {
    return __half22float2(*(__half2*)&u);
}
__device__ __forceinline__ float elu1(float v) { return (v > 0.f) ? v : expm1f(v); }

#define MMA_BF16(d, a, b)                                                     \
    asm volatile(                                                             \
        "mma.sync.aligned.m16n8k16.row.col.f32.bf16.bf16.f32 "                \
        "{%0,%1,%2,%3}, {%4,%5,%6,%7}, {%8,%9}, {%0,%1,%2,%3};\n"             \
        : "+f"((d)[0]), "+f"((d)[1]), "+f"((d)[2]), "+f"((d)[3])              \
        : "r"((a)[0]), "r"((a)[1]), "r"((a)[2]), "r"((a)[3]),                 \
          "r"((b)[0]), "r"((b)[1]))

#define MMA_F16(d, a, b)                                                      \
    asm volatile(                                                             \
        "mma.sync.aligned.m16n8k16.row.col.f32.f16.f16.f32 "                  \
        "{%0,%1,%2,%3}, {%4,%5,%6,%7}, {%8,%9}, {%0,%1,%2,%3};\n"             \
        : "+f"((d)[0]), "+f"((d)[1]), "+f"((d)[2]), "+f"((d)[3])              \
        : "r"((a)[0]), "r"((a)[1]), "r"((a)[2]), "r"((a)[3]),                 \
          "r"((b)[0]), "r"((b)[1]))

__device__ __forceinline__ void atomMaxF(int* a, float v) {
    int iv = __float_as_int(v);
    if (iv >= 0) atomicMax(a, iv);
    else         atomicMin((unsigned int*)a, (unsigned int)iv);
}

// ---------------- init ----------------------------------------------------------
__global__ void k_init0() {
    int t = threadIdx.x;
    if (t < NG) {
        g_mx[t]  = (int)0xFF800000;
        g_sum[t] = 0.f;
        g_pk[t]  = 0ull;
    }
}

// ---------------- Wc = Wr3 @ Wp1 (packed fp16 pairs), bc = br3@Wp1+bp1 -----------
__global__ void k_wc(const float* __restrict__ Wr3, const float* __restrict__ br3,
                     const float* __restrict__ Wp1, const float* __restrict__ bp1) {
    int t = blockIdx.x * blockDim.x + threadIdx.x;
    if (t >= 128 * 128) return;
    int kp = t >> 7, c = t & 127;
    float s0 = 0.f, s1 = 0.f;
    #pragma unroll 8
    for (int m = 0; m < 128; m++) {
        float w = Wp1[m * 128 + c];
        s0 += Wr3[(2 * kp) * 128 + m] * w;
        s1 += Wr3[(2 * kp + 1) * 128 + m] * w;
    }
    g_Wcp[kp * 128 + c] = cvt_h2(s0, s1);
    if (t < 128) {
        float b = bp1[t];
        #pragma unroll 8
        for (int m = 0; m < 128; m++) b += br3[m] * Wp1[m * 128 + t];
        g_bc[t] = b;
    }
}

// ---------------- pack Wr2 + Wr1 in one launch -------------------------------------
__global__ void k_pack12(const float* __restrict__ Wr2, const float* __restrict__ Wr1) {
    int t = blockIdx.x * blockDim.x + threadIdx.x;
    if (t < 256 * 256) {
        int kp = t >> 8, c = t & 255;
        g_W2p[t] = cvt_h2(Wr2[(2 * kp) * 256 + c], Wr2[(2 * kp + 1) * 256 + c]);
    } else if (t < 256 * 256 + 128 * 512) {
        int t2 = t - 256 * 256;
        int kp = t2 >> 9, c = t2 & 511;
        g_W1p[t2] = cvt_h2(Wr1[(2 * kp) * 512 + c], Wr1[(2 * kp + 1) * 512 + c]);
    }
}

// ---------------- per-edge segment / label precompute -------------------------------
__global__ void k_seg(const int* __restrict__ ei, const int* __restrict__ bv,
                      const int* __restrict__ y) {
    int e = blockIdx.x * blockDim.x + threadIdx.x;
    if (e >= EA) return;
    int s = __ldg(&ei[NOCP + e]);
    int g = __ldg(&bv[s]);
    g_seg[e] = g;
    g_lbl[e] = __ldg(&y[g]);
}

// =============================================================================
//   BF16x3 dense GEMM (128x128 tile, 256 thr) — S/M node transforms (accurate)
// =============================================================================
#define ASTR 12
#define BSTR 132

__global__ void __launch_bounds__(256)
tgemm_sm(const float* __restrict__ A,
         const float* __restrict__ B0, const float* __restrict__ B1,
         float* __restrict__ C0, float* __restrict__ C1, int M) {
    const int N = HD, K = HD;
    const float* B = blockIdx.z ? B1 : B0;
    float* C = blockIdx.z ? C1 : C0;

    __shared__ uint32_t Ah[2][128][ASTR], Al[2][128][ASTR];
    __shared__ uint32_t Bh[2][8][BSTR],  Bl[2][8][BSTR];

    const int tid = threadIdx.x;
    const int bm = blockIdx.y * 128;

    const int wid = tid >> 5, lane = tid & 31;
    const int gid = lane >> 2, tg = lane & 3;
    const int wm = (wid >> 2) * 64, wn = (wid & 3) * 32;

    const int arow = tid >> 1,  acq = (tid & 1) * 8;
    const int bkp  = tid >> 5,  bnq = (tid & 31) * 4;

    float4 pa0, pa1, pb0, pb1;
    auto loadG = [&](int k0) {
        int gr = bm + arow;
        if (gr < M) {
            pa0 = *(const float4*)&A[(size_t)gr * K + k0 + acq];
            pa1 = *(const float4*)&A[(size_t)gr * K + k0 + acq + 4];
        } else {
            pa0 = make_float4(0.f, 0.f, 0.f, 0.f); pa1 = pa0;
        }
        pb0 = *(const float4*)&B[(size_t)(k0 + 2 * bkp)     * N + bnq];
        pb1 = *(const float4*)&B[(size_t)(k0 + 2 * bkp + 1) * N + bnq];
    };
    auto storeS = [&](int buf) {
        uint32_t h0, h1, h2, h3, l0, l1, l2, l3;
        cvt_pair(pa0.x, pa0.y, h0, l0);
        cvt_pair(pa0.z, pa0.w, h1, l1);
        cvt_pair(pa1.x, pa1.y, h2, l2);
        cvt_pair(pa1.z, pa1.w, h3, l3);
        int kp = acq >> 1;
        *(uint4*)&Ah[buf][arow][kp] = make_uint4(h0, h1, h2, h3);
        *(uint4*)&Al[buf][arow][kp] = make_uint4(l0, l1, l2, l3);
        cvt_pair(pb0.x, pb1.x, h0, l0);
        cvt_pair(pb0.y, pb1.y, h1, l1);
        cvt_pair(pb0.z, pb1.z, h2, l2);
        cvt_pair(pb0.w, pb1.w, h3, l3);
        *(uint4*)&Bh[buf][bkp][bnq] = make_uint4(h0, h1, h2, h3);
        *(uint4*)&Bl[buf][bkp][bnq] = make_uint4(l0, l1, l2, l3);
    };

    float acc[4][4][4];
    #pragma unroll
    for (int i = 0; i < 4; i++)
        #pragma unroll
        for (int j = 0; j < 4; j++)
            #pragma unroll
            for (int r = 0; r < 4; r++) acc[i][j][r] = 0.f;

    loadG(0); storeS(0); __syncthreads();

    const int ntiles = K >> 4;
    for (int t = 0; t < ntiles; t++) {
        const int cur = t & 1;
        if (t + 1 < ntiles) loadG((t + 1) << 4);

        uint32_t ahf[4][4], alf[4][4], bhf[4][2], blf[4][2];
        #pragma unroll
        for (int mt = 0; mt < 4; mt++) {
            int r0 = wm + mt * 16 + gid;
            ahf[mt][0] = Ah[cur][r0    ][tg    ]; alf[mt][0] = Al[cur][r0    ][tg    ];
            ahf[mt][1] = Ah[cur][r0 + 8][tg    ]; alf[mt][1] = Al[cur][r0 + 8][tg    ];
            ahf[mt][2] = Ah[cur][r0    ][tg + 4]; alf[mt][2] = Al[cur][r0    ][tg + 4];
            ahf[mt][3] = Ah[cur][r0 + 8][tg + 4]; alf[mt][3] = Al[cur][r0 + 8][tg + 4];
        }
        #pragma unroll
        for (int nt = 0; nt < 4; nt++) {
            int c = wn + nt * 8 + gid;
            bhf[nt][0] = Bh[cur][tg    ][c]; blf[nt][0] = Bl[cur][tg    ][c];
            bhf[nt][1] = Bh[cur][tg + 4][c]; blf[nt][1] = Bl[cur][tg + 4][c];
        }
        #pragma unroll
        for (int mt = 0; mt < 4; mt++)
            #pragma unroll
            for (int nt = 0; nt < 4; nt++) {
                MMA_BF16(acc[mt][nt], ahf[mt], bhf[nt]);
                MMA_BF16(acc[mt][nt], ahf[mt], blf[nt]);
                MMA_BF16(acc[mt][nt], alf[mt], bhf[nt]);
            }

        if (t + 1 < ntiles) { storeS(cur ^ 1); __syncthreads(); }
    }

    #pragma unroll
    for (int mt = 0; mt < 4; mt++) {
        int r0 = bm + wm + mt * 16 + gid;
        #pragma unroll
        for (int nt = 0; nt < 4; nt++) {
            int c = wn + nt * 8 + tg * 2;
            if (r0 < M)
                *(float2*)&C[(size_t)r0 * N + c] = make_float2(acc[mt][nt][0], acc[mt][nt][1]);
            if (r0 + 8 < M)
                *(float2*)&C[(size_t)(r0 + 8) * N + c] = make_float2(acc[mt][nt][2], acc[mt][nt][3]);
        }
    }
}

// =============================================================================
//  tgemm_wide2: fused D-computation + persistent-A GEMM.
//  One block per 128 node rows; A = split(elu(S+b+aggO+aggR)-elu(S+b+aggO))
//  built ONCE in smem (full K=128); loops over 4 output chunks
//  (P/Q halves x two 256-col halves of Wr1) with a double-buffered B ring.
// =============================================================================
#define AW2 68                      // A smem row stride (words), conflict-free frags
#define DSMEM_WIDE2 (2 * 128 * AW2 * 4 + 2 * 8 * 260 * 4)   // 86272

__global__ void __launch_bounds__(512)
tgemm_wide2(const float* __restrict__ bg, uint32_t* __restrict__ P16,
            uint32_t* __restrict__ Q16, int M) {
    extern __shared__ char dsmw[];
    uint32_t (*Ah)[AW2]    = (uint32_t(*)[AW2])(dsmw);
    uint32_t (*Al)[AW2]    = (uint32_t(*)[AW2])(dsmw + 128 * AW2 * 4);
    uint32_t (*Bp)[8][260] = (uint32_t(*)[8][260])(dsmw + 2 * 128 * AW2 * 4);

    __shared__ float sbg[128];

    const int tid = threadIdx.x;
    const int bm = blockIdx.y * 128;

    const int wid = tid >> 5, lane = tid & 31;
    const int gid = lane >> 2, tg = lane & 3;
    const int wr = wid >> 2, wc = wid & 3;

    if (tid < 128) sbg[tid] = bg[tid];
    __syncthreads();

    // -------- build A (elu-diff) once: 128 rows x 128 cols --------
    #pragma unroll
    for (int it = 0; it < 8; it++) {
        int seg = it * 512 + tid;
        int row = seg >> 5;
        int c4  = (seg & 31) * 4;
        int gr = bm + row;
        float4 d;
        if (gr < M) {
            size_t off = (size_t)gr * HD + c4;
            float4 s  = *(const float4*)&g_S[off];
            float4 ao = *(const float4*)&g_aggO[off];
            float4 ar = *(const float4*)&g_aggR[off];
            float b0 = s.x + sbg[c4]     + ao.x;
            float b1 = s.y + sbg[c4 + 1] + ao.y;
            float b2 = s.z + sbg[c4 + 2] + ao.z;
            float b3 = s.w + sbg[c4 + 3] + ao.w;
            d.x = elu1(b0 + ar.x) - elu1(b0);
            d.y = elu1(b1 + ar.y) - elu1(b1);
            d.z = elu1(b2 + ar.z) - elu1(b2);
            d.w = elu1(b3 + ar.w) - elu1(b3);
        } else d = make_float4(0.f, 0.f, 0.f, 0.f);
        uint32_t h0, l0, h1, l1;
        cvt_splith(d.x, d.y, h0, l0);
        cvt_splith(d.z, d.w, h1, l1);
        int kp = c4 >> 1;
        Ah[row][kp] = h0; Ah[row][kp + 1] = h1;
        Al[row][kp] = l0; Al[row][kp + 1] = l1;
    }
    __syncthreads();

    const int bkp = tid >> 6;
    const int bc4 = (tid & 63) * 4;

    for (int ch = 0; ch < 4; ch++) {
        const int kpoff = (ch >> 1) * 64;      // P vs Q half of Wr1 rows
        const int bn    = (ch & 1) * 256;      // column half
        uint32_t* C16 = (ch >> 1) ? Q16 : P16;

        uint4 pbh;
        auto loadB = [&](int t) {
            int kpg = kpoff + t * 8 + bkp;
            pbh = *(const uint4*)&g_W1p[kpg * 512 + bn + bc4];
        };
        auto storeB = [&](int buf) {
            *(uint4*)&Bp[buf][bkp][bc4] = pbh;
        };

        float acc[2][8][4];
        #pragma unroll
        for (int i = 0; i < 2; i++)
            #pragma unroll
            for (int j = 0; j < 8; j++)
                #pragma unroll
                for (int r = 0; r < 4; r++) acc[i][j][r] = 0.f;

        loadB(0); storeB(0); __syncthreads();

        for (int t = 0; t < 8; t++) {
            const int cur = t & 1;
            if (t + 1 < 8) loadB(t + 1);

            const int kb = t * 8;
            uint32_t ahf[2][4], alf[2][4];
            #pragma unroll
            for (int mt = 0; mt < 2; mt++) {
                int r0 = wr * 32 + mt * 16 + gid;
                ahf[mt][0] = Ah[r0    ][kb + tg];     alf[mt][0] = Al[r0    ][kb + tg];
                ahf[mt][1] = Ah[r0 + 8][kb + tg];     alf[mt][1] = Al[r0 + 8][kb + tg];
                ahf[mt][2] = Ah[r0    ][kb + tg + 4]; alf[mt][2] = Al[r0    ][kb + tg + 4];
                ahf[mt][3] = Ah[r0 + 8][kb + tg + 4]; alf[mt][3] = Al[r0 + 8][kb + tg + 4];
            }
            #pragma unroll
            for (int nt = 0; nt < 8; nt++) {
                int c = wc * 64 + nt * 8 + gid;
                uint32_t bh[2];
                bh[0] = Bp[cur][tg][c]; bh[1] = Bp[cur][tg + 4][c];
                #pragma unroll
                for (int mt = 0; mt < 2; mt++) {
                    MMA_F16(acc[mt][nt], ahf[mt], bh);
                    MMA_F16(acc[mt][nt], alf[mt], bh);
                }
            }
            if (t + 1 < 8) { storeB(cur ^ 1); __syncthreads(); }
        }

        #pragma unroll
        for (int mt = 0; mt < 2; mt++) {
            int ra = bm + wr * 32 + mt * 16 + gid;
            #pragma unroll
            for (int nt = 0; nt < 8; nt++) {
                int c = bn + wc * 64 + nt * 8 + tg * 2;
                if (ra < M)
                    C16[(size_t)ra * 256 + (c >> 1)] = cvt_h2(acc[mt][nt][0], acc[mt][nt][1]);
                if (ra + 8 < M)
                    C16[(size_t)(ra + 8) * 256 + (c >> 1)] = cvt_h2(acc[mt][nt][2], acc[mt][nt][3]);
            }
        }
        __syncthreads();   // B buffers reused by next chunk
    }
}

// =============================================================================
//  gemm23_sel: stage1 A single fp16 plane (P/Q fp16), stage2 T hi/lo split.
// =============================================================================
#define DSMEM_G23 164096

__global__ void __launch_bounds__(512)
gemm23_sel(const int* __restrict__ esrc, const int* __restrict__ edst,
           const uint32_t* __restrict__ Pm, const uint32_t* __restrict__ Qm,
           const float* __restrict__ br1, const float* __restrict__ br2,
           const float* __restrict__ Wp2, const float* __restrict__ bp2) {
    extern __shared__ char dsm[];
    uint32_t (*Th)[132] = (uint32_t(*)[132])(dsm);
    uint32_t (*Tl)[132] = (uint32_t(*)[132])(dsm + 67584);
    char* s1 = dsm + 135168;
    uint32_t (*Ah)[128][12] = (uint32_t(*)[128][12])(s1);
    uint32_t (*Bp)[8][260]  = (uint32_t(*)[8][260]) (s1 + 12288);
    uint32_t (*B2p)[8][132] = (uint32_t(*)[8][132]) (s1);          // reuses stage-1 region

    __shared__ float sW[1280];
    __shared__ float sbc[128];
    __shared__ float sbr1[512];
    __shared__ float sbr2[256];
    __shared__ float red[128][4];
    __shared__ int   smx[NG];

    const int tid = threadIdx.x;
    const int bm = blockIdx.x * 128;
    const int wid = tid >> 5, lane = tid & 31;
    const int gid = lane >> 2, tg = lane & 3;
    const int wr = wid >> 2, wc = wid & 3;

    if (tid < 128) sbc[tid] = g_bc[tid];
    if (tid < 256) sbr2[tid] = br2[tid];
    if (tid < NG)  smx[tid] = (int)0xFF800000;
    sbr1[tid] = br1[tid];
    for (int i = tid; i < 1280; i += 512) sW[i] = Wp2[i];

    // ---------------- stage 1 (K=512, N=256), A single-plane fp16 ----------------
    const int arow = tid >> 2;
    const int akp  = (tid & 3) * 2;
    const int bkp  = tid >> 6;
    const int bc4  = (tid & 63) * 4;

    const int src = __ldg(&esrc[bm + arow]);
    const int dst = __ldg(&edst[bm + arow]);

    uint32_t ah0, ah1;
    uint4 pbh;
    auto loadG1 = [&](int k0) {
        int kp0 = (k0 >> 1) + (tid & 3) * 2;
        uint2 pp = *(const uint2*)&Pm[(size_t)src * 256 + kp0];
        uint2 qq = *(const uint2*)&Qm[(size_t)dst * 256 + kp0];
        float2 p0 = h2f2(pp.x), p1 = h2f2(pp.y);
        float2 q0 = h2f2(qq.x), q1 = h2f2(qq.y);
        int kb = k0 + (tid & 3) * 4;
        float e0 = elu1(p0.x + q0.x + sbr1[kb]);
        float e1 = elu1(p0.y + q0.y + sbr1[kb + 1]);
        float e2 = elu1(p1.x + q1.x + sbr1[kb + 2]);
        float e3 = elu1(p1.y + q1.y + sbr1[kb + 3]);
        ah0 = cvt_h2(e0, e1);
        ah1 = cvt_h2(e2, e3);
        int kpg = (k0 >> 1) + bkp;
        pbh = *(const uint4*)&g_W2p[kpg * 256 + bc4];
    };
    auto storeS1 = [&](int buf) {
        Ah[buf][arow][akp]     = ah0;
        Ah[buf][arow][akp + 1] = ah1;
        *(uint4*)&Bp[buf][bkp][bc4] = pbh;
    };

    float acc[2][8][4];
    #pragma unroll
    for (int i = 0; i < 2; i++)
        #pragma unroll
        for (int j = 0; j < 8; j++)
            #pragma unroll
            for (int r = 0; r < 4; r++) acc[i][j][r] = 0.f;

    loadG1(0); storeS1(0); __syncthreads();

    for (int t = 0; t < 32; t++) {
        const int cur = t & 1;
        if (t + 1 < 32) loadG1((t + 1) << 4);

        uint32_t ahf[2][4];
        #pragma unroll
        for (int mt = 0; mt < 2; mt++) {
            int r0 = wr * 32 + mt * 16 + gid;
            ahf[mt][0] = Ah[cur][r0    ][tg];
            ahf[mt][1] = Ah[cur][r0 + 8][tg];
            ahf[mt][2] = Ah[cur][r0    ][tg + 4];
            ahf[mt][3] = Ah[cur][r0 + 8][tg + 4];
        }
        #pragma unroll
        for (int nt = 0; nt < 8; nt++) {
            int c = wc * 64 + nt * 8 + gid;
            uint32_t bh[2];
            bh[0] = Bp[cur][tg][c]; bh[1] = Bp[cur][tg + 4][c];
            #pragma unroll
            for (int mt = 0; mt < 2; mt++)
                MMA_F16(acc[mt][nt], ahf[mt], bh);
        }
        if (t + 1 < 32) { storeS1(cur ^ 1); __syncthreads(); }
    }

    // pack T = elu(acc + br2) into Th/Tl (fp16 hi/lo pairs)
    #pragma unroll
    for (int mt = 0; mt < 2; mt++) {
        int ra = wr * 32 + mt * 16 + gid, rb = ra + 8;
        #pragma unroll
        for (int nt = 0; nt < 8; nt++) {
            int c = wc * 64 + nt * 8 + tg * 2;
            float e0 = elu1(acc[mt][nt][0] + sbr2[c]);
            float e1 = elu1(acc[mt][nt][1] + sbr2[c + 1]);
            float e2 = elu1(acc[mt][nt][2] + sbr2[c]);
            float e3 = elu1(acc[mt][nt][3] + sbr2[c + 1]);
            uint32_t h, l;
            cvt_splith(e0, e1, h, l); Th[ra][c >> 1] = h; Tl[ra][c >> 1] = l;
            cvt_splith(e2, e3, h, l); Th[rb][c >> 1] = h; Tl[rb][c >> 1] = l;
        }
    }
    __syncthreads();   // T complete; stage-1 buffers free

    // ---------------- stage 2 (K=256, N=128) ----------------
    const int b2kp = tid >> 6;
    const int b2c  = (tid & 63) * 2;

    uint2 qbh;
    auto loadG2 = [&](int s) {
        int kpg = s * 8 + b2kp;
        qbh = *(const uint2*)&g_Wcp[kpg * 128 + b2c];
    };
    auto storeS2 = [&](int buf) {
        *(uint2*)&B2p[buf][b2kp][b2c] = qbh;
    };

    float acc2[2][4][4];
    #pragma unroll
    for (int i = 0; i < 2; i++)
        #pragma unroll
        for (int j = 0; j < 4; j++)
            #pragma unroll
            for (int r = 0; r < 4; r++) acc2[i][j][r] = 0.f;

    loadG2(0); storeS2(0); __syncthreads();

    for (int s = 0; s < 16; s++) {
        const int cur = s & 1;
        if (s + 1 < 16) loadG2(s + 1);

        uint32_t ahf[2][4], alf[2][4];
        const int kb = s * 8;
        #pragma unroll
        for (int mt = 0; mt < 2; mt++) {
            int r0 = wr * 32 + mt * 16 + gid;
            ahf[mt][0] = Th[r0    ][kb + tg];     alf[mt][0] = Tl[r0    ][kb + tg];
            ahf[mt][1] = Th[r0 + 8][kb + tg];     alf[mt][1] = Tl[r0 + 8][kb + tg];
            ahf[mt][2] = Th[r0    ][kb + tg + 4]; alf[mt][2] = Tl[r0    ][kb + tg + 4];
            ahf[mt][3] = Th[r0 + 8][kb + tg + 4]; alf[mt][3] = Tl[r0 + 8][kb + tg + 4];
        }
        #pragma unroll
        for (int nt = 0; nt < 4; nt++) {
            int c = wc * 32 + nt * 8 + gid;
            uint32_t bh[2];
            bh[0] = B2p[cur][tg][c]; bh[1] = B2p[cur][tg + 4][c];
            #pragma unroll
            for (int mt = 0; mt < 2; mt++) {
                MMA_F16(acc2[mt][nt], ahf[mt], bh);
                MMA_F16(acc2[mt][nt], alf[mt], bh);
            }
        }
        if (s + 1 < 16) { storeS2(cur ^ 1); __syncthreads(); }
    }

    // epilogue: h = elu(acc2 + bc); per-row dot with Wp2[:, lbl]
    #pragma unroll
    for (int mt = 0; mt < 2; mt++) {
        int ra = wr * 32 + mt * 16 + gid, rb = ra + 8;
        int lbla = g_lbl[bm + ra], lblb = g_lbl[bm + rb];
        float pa = 0.f, pb = 0.f;
        #pragma unroll
        for (int nt = 0; nt < 4; nt++) {
            int c = wc * 32 + nt * 8 + tg * 2;
            float h;
            h = elu1(acc2[mt][nt][0] + sbc[c]);     pa += h * sW[c * 10 + lbla];
            h = elu1(acc2[mt][nt][1] + sbc[c + 1]); pa += h * sW[(c + 1) * 10 + lbla];
            h = elu1(acc2[mt][nt][2] + sbc[c]);     pb += h * sW[c * 10 + lblb];
            h = elu1(acc2[mt][nt][3] + sbc[c + 1]); pb += h * sW[(c + 1) * 10 + lblb];
        }
        pa += __shfl_xor_sync(0xffffffffu, pa, 1);
        pa += __shfl_xor_sync(0xffffffffu, pa, 2);
        pb += __shfl_xor_sync(0xffffffffu, pb, 1);
        pb += __shfl_xor_sync(0xffffffffu, pb, 2);
        if (tg == 0) { red[ra][wc] = pa; red[rb][wc] = pb; }
    }
    __syncthreads();
    if (tid < 128) {
        float s = red[tid][0] + red[tid][1] + red[tid][2] + red[tid][3]
                + __ldg(&bp2[g_lbl[bm + tid]]);
        g_sel[bm + tid] = s;
        atomMaxF(&smx[g_seg[bm + tid]], s);
    }
    __syncthreads();
    if (tid < NG) {
        float v = __int_as_float(smx[tid]);
        if (v > -1e37f) atomMaxF(&g_mx[tid], v);
    }
}

// ---------------- edge scatter-add (one red.v4 per edge-lane) --------------------
__global__ void k_scatter(const int* __restrict__ ei) {
    int t = blockIdx.x * blockDim.x + threadIdx.x;
    if (t >= NE * 32) return;
    int e = t >> 5, v = t & 31;
    int s = __ldg(&ei[e]);
    int d = __ldg(&ei[NE + e]);
    float4 m = *(const float4*)&g_Mm[(size_t)s * HD + v * 4];
    float* dst4 = (e < NOCP) ? &g_aggO[(size_t)d * HD + v * 4]
                             : &g_aggR[(size_t)d * HD + v * 4];
    asm volatile("red.global.add.v4.f32 [%0], {%1,%2,%3,%4};"
                 :: "l"(dst4), "f"(m.x), "f"(m.y), "f"(m.z), "f"(m.w) : "memory");
}

// ---------------- segment softmax remainder --------------------------------------
__global__ void k_ex() {
    __shared__ float ss[NG];
    int tid = threadIdx.x;
    if (tid < NG) ss[tid] = 0.f;
    __syncthreads();
    int e = blockIdx.x * blockDim.x + tid;
    if (e < EA) {
        int g = g_seg[e];
        float v = expf(g_sel[e] - __int_as_float(g_mx[g]));
        g_ex[e] = v;
        atomicAdd(&ss[g], v);
    }
    __syncthreads();
    if (tid < NG && ss[tid] != 0.f) atomicAdd(&g_sum[tid], ss[tid]);
}

// probs + fused (pmax, argmin-index) via packed 64-bit max
__global__ void k_probs(float* __restrict__ out) {
    __shared__ unsigned long long sp[NG];
    int tid = threadIdx.x;
    if (tid < NG) sp[tid] = 0ull;
    __syncthreads();
    int e = blockIdx.x * blockDim.x + tid;
    if (e < EA) {
        int g = g_seg[e];
        float p = g_ex[e] / g_sum[g];
        out[e] = p;
        unsigned long long pk =
            ((unsigned long long)__float_as_uint(p) << 32) | (unsigned int)(EA - e);
        atomicMax(&sp[g], pk);
    }
    __syncthreads();
    if (tid < NG && sp[tid] != 0ull) atomicMax(&g_pk[tid], sp[tid]);
}

__global__ void k_tail(float* __restrict__ out) {
    int t = threadIdx.x;
    if (t < NG) {
        unsigned long long pk = g_pk[t];
        out[EA + t]      = __uint_as_float((unsigned int)(pk >> 32));
        out[EA + NG + t] = (float)(EA - (int)(pk & 0xFFFFFFFFu));
    }
}

// ---------------- launch ----------------------------------------------------------
extern "C" void kernel_launch(void* const* d_in, const int* in_sizes, int n_in,
                              void* d_out, int out_size) {
    const int pb = n_in - 13;
    const float* x      = (const float*)d_in[0];
    const int*   ei     = (const int*)  d_in[1];
    const int*   bv     = (const int*)  d_in[2];
    const int*   y      = (const int*)  d_in[3];
    const float* W_self = (const float*)d_in[pb + 0];
    const float* W_nbr  = (const float*)d_in[pb + 1];
    const float* b_gnn  = (const float*)d_in[pb + 2];
    const float* Wr1    = (const float*)d_in[pb + 3];
    const float* br1    = (const float*)d_in[pb + 4];
    const float* Wr2    = (const float*)d_in[pb + 5];
    const float* br2    = (const float*)d_in[pb + 6];
    const float* Wr3    = (const float*)d_in[pb + 7];
    const float* br3    = (const float*)d_in[pb + 8];
    const float* Wp1    = (const float*)d_in[pb + 9];
    const float* bp1    = (const float*)d_in[pb + 10];
    const float* Wp2    = (const float*)d_in[pb + 11];
    const float* bp2    = (const float*)d_in[pb + 12];
    float* out = (float*)d_out;

    void *pS, *pM, *pP, *pQ, *pAR, *pAO;
    cudaGetSymbolAddress(&pS,  g_S);
    cudaGetSymbolAddress(&pM,  g_Mm);
    cudaGetSymbolAddress(&pP,  g_P16);
    cudaGetSymbolAddress(&pQ,  g_Q16);
    cudaGetSymbolAddress(&pAR, g_aggR);
    cudaGetSymbolAddress(&pAO, g_aggO);

    cudaFuncSetAttribute(gemm23_sel,  cudaFuncAttributeMaxDynamicSharedMemorySize, DSMEM_G23);
    cudaFuncSetAttribute(tgemm_wide2, cudaFuncAttributeMaxDynamicSharedMemorySize, DSMEM_WIDE2);

    const int T = 256;

    cudaMemsetAsync(pAR, 0, (size_t)NN * HD * sizeof(float));
    cudaMemsetAsync(pAO, 0, (size_t)NN * HD * sizeof(float));
    k_init0 <<<1, 64>>>();
    k_wc    <<<(128 * 128 + T - 1) / T, T>>>(Wr3, br3, Wp1, bp1);
    k_pack12<<<(256 * 256 + 128 * 512 + T - 1) / T, T>>>(Wr2, Wr1);
    k_seg   <<<(EA + T - 1) / T, T>>>(ei, bv, y);

    // node transform GEMMs: S = x@W_self, M = x@W_nbr
    tgemm_sm<<<dim3(1, (NN + 127) / 128, 2), T>>>(x, W_self, W_nbr,
                                                  (float*)pS, (float*)pM, NN);

    k_scatter<<<(NE * 32 + T - 1) / T, T>>>(ei);

    // fused D-computation + P/Q GEMMs (persistent A, 4 output chunks)
    tgemm_wide2<<<dim3(1, (NN + 127) / 128), 512, DSMEM_WIDE2>>>(
        b_gnn, (uint32_t*)pP, (uint32_t*)pQ, NN);

    // fused GEMM2 + GEMM3 + sel + segment-max
    gemm23_sel<<<EA / 128, 512, DSMEM_G23>>>(
        ei + NOCP, ei + NE + NOCP, (const uint32_t*)pP, (const uint32_t*)pQ,
        br1, br2, Wp2, bp2);

    // segment softmax + fused argmax
    const int segBlocks = (EA + T - 1) / T;
    k_ex   <<<segBlocks, T>>>();
    k_probs<<<segBlocks, T>>>(out);
    k_tail <<<1, 64>>>(out);
}

// round 12
// speedup vs baseline: 1.0379x; 1.0379x over previous
#include <cuda_runtime.h>
#include <cuda_bf16.h>
#include <cuda_fp16.h>
#include <math.h>
#include <stdint.h>

#define NN   50000
#define NE   262144
#define NOCP 32768
#define EA   (NE - NOCP)      // 229376
#define NG   64
#define HD   128

// ---------------- scratch ----------------------------------------------------
__device__ float g_S   [NN * HD];
__device__ float g_Mm  [NN * HD];
__device__ float g_aggR[NN * HD];
__device__ float g_aggO[NN * HD];
__device__ uint32_t g_P16[(size_t)NN * 256];   // P as fp16 pairs
__device__ uint32_t g_Q16[(size_t)NN * 256];   // Q as fp16 pairs
__device__ float g_sel [EA];
__device__ int   g_seg [EA];
__device__ int   g_lbl [EA];
__device__ float g_bc  [128];
__device__ uint32_t g_W2p[256 * 256];   // Wr2 fp16 pairs (kp x 256)
__device__ uint32_t g_Wcp[128 * 128];   // Wc  fp16 pairs (kp x 128)
__device__ uint32_t g_W1p[128 * 512];   // Wr1 fp16 pairs (kp x 512)
__device__ int   g_mx  [NG];
__device__ float g_sum [NG];
__device__ unsigned long long g_pk[NG]; // packed (prob bits << 32) | (EA - e)

// ---------------- helpers -----------------------------------------------------
__device__ __forceinline__ void cvt_pair(float f0, float f1, uint32_t& h, uint32_t& l) {
    __nv_bfloat162 H = __floats2bfloat162_rn(f0, f1);
    float2 Hf = __bfloat1622float2(H);
    __nv_bfloat162 L = __floats2bfloat162_rn(f0 - Hf.x, f1 - Hf.y);
    h = *(uint32_t*)&H;
    l = *(uint32_t*)&L;
}
__device__ __forceinline__ uint32_t cvt_h2(float f0, float f1) {
    __half2 H = __floats2half2_rn(f0, f1);
    return *(uint32_t*)&H;
}
__device__ __forceinline__ void cvt_splith(float f0, float f1, uint32_t& h, uint32_t& l) {
    __half2 H = __floats2half2_rn(f0, f1);
    float2 Hf = __half22float2(H);
    __half2 L = __floats2half2_rn(f0 - Hf.x, f1 - Hf.y);
    h = *(uint32_t*)&H;
    l = *(uint32_t*)&L;
}
__device__ __forceinline__ float2 h2f2(uint32_t u) {
    return __half22float2(*(__half2*)&u);
}
__device__ __forceinline__ float elu1(float v) { return (v > 0.f) ? v : expm1f(v); }

#define MMA_BF16(d, a, b)                                                     \
    asm volatile(                                                             \
        "mma.sync.aligned.m16n8k16.row.col.f32.bf16.bf16.f32 "                \
        "{%0,%1,%2,%3}, {%4,%5,%6,%7}, {%8,%9}, {%0,%1,%2,%3};\n"             \
        : "+f"((d)[0]), "+f"((d)[1]), "+f"((d)[2]), "+f"((d)[3])              \
        : "r"((a)[0]), "r"((a)[1]), "r"((a)[2]), "r"((a)[3]),                 \
          "r"((b)[0]), "r"((b)[1]))

#define MMA_F16(d, a, b)                                                      \
    asm volatile(                                                             \
        "mma.sync.aligned.m16n8k16.row.col.f32.f16.f16.f32 "                  \
        "{%0,%1,%2,%3}, {%4,%5,%6,%7}, {%8,%9}, {%0,%1,%2,%3};\n"             \
        : "+f"((d)[0]), "+f"((d)[1]), "+f"((d)[2]), "+f"((d)[3])              \
        : "r"((a)[0]), "r"((a)[1]), "r"((a)[2]), "r"((a)[3]),                 \
          "r"((b)[0]), "r"((b)[1]))

__device__ __forceinline__ void atomMaxF(int* a, float v) {
    int iv = __float_as_int(v);
    if (iv >= 0) atomicMax(a, iv);
    else         atomicMin((unsigned int*)a, (unsigned int)iv);
}

// ---------------- merged prep: init + pack(W2,W1) + seg -------------------------
#define PACK_BLKS 512                   // covers 65536 + 65536 elements @256thr
#define SEG_BLKS  ((EA + 255) / 256)    // 896

__global__ void k_prep(const float* __restrict__ Wr2, const float* __restrict__ Wr1,
                       const int* __restrict__ ei, const int* __restrict__ bv,
                       const int* __restrict__ y) {
    int b = blockIdx.x;
    if (b == 0 && threadIdx.x < NG) {
        int t = threadIdx.x;
        g_mx[t]  = (int)0xFF800000;
        g_sum[t] = 0.f;
        g_pk[t]  = 0ull;
    }
    if (b < PACK_BLKS) {
        int t = b * 256 + threadIdx.x;
        if (t < 256 * 256) {
            int kp = t >> 8, c = t & 255;
            g_W2p[t] = cvt_h2(Wr2[(2 * kp) * 256 + c], Wr2[(2 * kp + 1) * 256 + c]);
        }
        int t2 = t;   // second 65536-range handled below with offset grid half
        t2 += PACK_BLKS * 256 * 0;        // (W1 handled by dedicated range)
    }
    // W1 pack occupies a second pass over the same 512 blocks
    if (b < PACK_BLKS) {
        int t = b * 256 + threadIdx.x;    // 0..131071
        int t1 = t + 131072 - 65536;      // map blocks 256..511 to W1 low half
        (void)t1;
    }
    // simpler: every block in [0, PACK_BLKS) packs BOTH halves at stride
    if (b < PACK_BLKS) {
        int t = b * 256 + threadIdx.x;    // 0..131071 over 512 blocks? (512*256=131072)
        if (t >= 65536 && t < 131072) {
            int t2 = t - 65536;           // 0..65535 -> first half of W1
            int kp = t2 >> 9, c = t2 & 511;
            g_W1p[t2] = cvt_h2(Wr1[(2 * kp) * 512 + c], Wr1[(2 * kp + 1) * 512 + c]);
        }
        // second half of W1 (65536..131071)
        int t3 = t + 65536;               // 65536..196607
        if (t3 >= 131072 && t3 < 196608) {
            int t4 = t3 - 131072 + 65536; // 65536..131071
            int kp = t4 >> 9, c = t4 & 511;
            g_W1p[t4] = cvt_h2(Wr1[(2 * kp) * 512 + c], Wr1[(2 * kp + 1) * 512 + c]);
        }
    } else {
        int e = (b - PACK_BLKS) * 256 + threadIdx.x;
        if (e < EA) {
            int s = __ldg(&ei[NOCP + e]);
            int g = __ldg(&bv[s]);
            g_seg[e] = g;
            g_lbl[e] = __ldg(&y[g]);
        }
    }
}

// ---------------- Wc = Wr3 @ Wp1 (packed fp16 pairs), bc = br3@Wp1+bp1 -----------
__global__ void k_wc(const float* __restrict__ Wr3, const float* __restrict__ br3,
                     const float* __restrict__ Wp1, const float* __restrict__ bp1) {
    int t = blockIdx.x * blockDim.x + threadIdx.x;
    if (t >= 128 * 128) return;
    int kp = t >> 7, c = t & 127;
    float s0 = 0.f, s1 = 0.f;
    #pragma unroll 8
    for (int m = 0; m < 128; m++) {
        float w = Wp1[m * 128 + c];
        s0 += Wr3[(2 * kp) * 128 + m] * w;
        s1 += Wr3[(2 * kp + 1) * 128 + m] * w;
    }
    g_Wcp[kp * 128 + c] = cvt_h2(s0, s1);
    if (t < 128) {
        float b = bp1[t];
        #pragma unroll 8
        for (int m = 0; m < 128; m++) b += br3[m] * Wp1[m * 128 + t];
        g_bc[t] = b;
    }
}

// =============================================================================
//   BF16x3 dense GEMM (128x128 tile, 256 thr) — S/M node transforms (accurate)
// =============================================================================
#define ASTR 12
#define BSTR 132

__global__ void __launch_bounds__(256)
tgemm_sm(const float* __restrict__ A,
         const float* __restrict__ B0, const float* __restrict__ B1,
         float* __restrict__ C0, float* __restrict__ C1, int M) {
    const int N = HD, K = HD;
    const float* B = blockIdx.z ? B1 : B0;
    float* C = blockIdx.z ? C1 : C0;

    __shared__ uint32_t Ah[2][128][ASTR], Al[2][128][ASTR];
    __shared__ uint32_t Bh[2][8][BSTR],  Bl[2][8][BSTR];

    const int tid = threadIdx.x;
    const int bm = blockIdx.y * 128;

    const int wid = tid >> 5, lane = tid & 31;
    const int gid = lane >> 2, tg = lane & 3;
    const int wm = (wid >> 2) * 64, wn = (wid & 3) * 32;

    const int arow = tid >> 1,  acq = (tid & 1) * 8;
    const int bkp  = tid >> 5,  bnq = (tid & 31) * 4;

    float4 pa0, pa1, pb0, pb1;
    auto loadG = [&](int k0) {
        int gr = bm + arow;
        if (gr < M) {
            pa0 = *(const float4*)&A[(size_t)gr * K + k0 + acq];
            pa1 = *(const float4*)&A[(size_t)gr * K + k0 + acq + 4];
        } else {
            pa0 = make_float4(0.f, 0.f, 0.f, 0.f); pa1 = pa0;
        }
        pb0 = *(const float4*)&B[(size_t)(k0 + 2 * bkp)     * N + bnq];
        pb1 = *(const float4*)&B[(size_t)(k0 + 2 * bkp + 1) * N + bnq];
    };
    auto storeS = [&](int buf) {
        uint32_t h0, h1, h2, h3, l0, l1, l2, l3;
        cvt_pair(pa0.x, pa0.y, h0, l0);
        cvt_pair(pa0.z, pa0.w, h1, l1);
        cvt_pair(pa1.x, pa1.y, h2, l2);
        cvt_pair(pa1.z, pa1.w, h3, l3);
        int kp = acq >> 1;
        *(uint4*)&Ah[buf][arow][kp] = make_uint4(h0, h1, h2, h3);
        *(uint4*)&Al[buf][arow][kp] = make_uint4(l0, l1, l2, l3);
        cvt_pair(pb0.x, pb1.x, h0, l0);
        cvt_pair(pb0.y, pb1.y, h1, l1);
        cvt_pair(pb0.z, pb1.z, h2, l2);
        cvt_pair(pb0.w, pb1.w, h3, l3);
        *(uint4*)&Bh[buf][bkp][bnq] = make_uint4(h0, h1, h2, h3);
        *(uint4*)&Bl[buf][bkp][bnq] = make_uint4(l0, l1, l2, l3);
    };

    float acc[4][4][4];
    #pragma unroll
    for (int i = 0; i < 4; i++)
        #pragma unroll
        for (int j = 0; j < 4; j++)
            #pragma unroll
            for (int r = 0; r < 4; r++) acc[i][j][r] = 0.f;

    loadG(0); storeS(0); __syncthreads();

    const int ntiles = K >> 4;
    for (int t = 0; t < ntiles; t++) {
        const int cur = t & 1;
        if (t + 1 < ntiles) loadG((t + 1) << 4);

        uint32_t ahf[4][4], alf[4][4], bhf[4][2], blf[4][2];
        #pragma unroll
        for (int mt = 0; mt < 4; mt++) {
            int r0 = wm + mt * 16 + gid;
            ahf[mt][0] = Ah[cur][r0    ][tg    ]; alf[mt][0] = Al[cur][r0    ][tg    ];
            ahf[mt][1] = Ah[cur][r0 + 8][tg    ]; alf[mt][1] = Al[cur][r0 + 8][tg    ];
            ahf[mt][2] = Ah[cur][r0    ][tg + 4]; alf[mt][2] = Al[cur][r0    ][tg + 4];
            ahf[mt][3] = Ah[cur][r0 + 8][tg + 4]; alf[mt][3] = Al[cur][r0 + 8][tg + 4];
        }
        #pragma unroll
        for (int nt = 0; nt < 4; nt++) {
            int c = wn + nt * 8 + gid;
            bhf[nt][0] = Bh[cur][tg    ][c]; blf[nt][0] = Bl[cur][tg    ][c];
            bhf[nt][1] = Bh[cur][tg + 4][c]; blf[nt][1] = Bl[cur][tg + 4][c];
        }
        #pragma unroll
        for (int mt = 0; mt < 4; mt++)
            #pragma unroll
            for (int nt = 0; nt < 4; nt++) {
                MMA_BF16(acc[mt][nt], ahf[mt], bhf[nt]);
                MMA_BF16(acc[mt][nt], ahf[mt], blf[nt]);
                MMA_BF16(acc[mt][nt], alf[mt], bhf[nt]);
            }

        if (t + 1 < ntiles) { storeS(cur ^ 1); __syncthreads(); }
    }

    #pragma unroll
    for (int mt = 0; mt < 4; mt++) {
        int r0 = bm + wm + mt * 16 + gid;
        #pragma unroll
        for (int nt = 0; nt < 4; nt++) {
            int c = wn + nt * 8 + tg * 2;
            if (r0 < M)
                *(float2*)&C[(size_t)r0 * N + c] = make_float2(acc[mt][nt][0], acc[mt][nt][1]);
            if (r0 + 8 < M)
                *(float2*)&C[(size_t)(r0 + 8) * N + c] = make_float2(acc[mt][nt][2], acc[mt][nt][3]);
        }
    }
}

// =============================================================================
//  tgemm_wide2: fused D-computation + persistent-A GEMM (P/Q, fp16 outputs)
// =============================================================================
#define AW2 68
#define DSMEM_WIDE2 (2 * 128 * AW2 * 4 + 2 * 8 * 260 * 4)   // 86272

__global__ void __launch_bounds__(512)
tgemm_wide2(const float* __restrict__ bg, uint32_t* __restrict__ P16,
            uint32_t* __restrict__ Q16, int M) {
    extern __shared__ char dsmw[];
    uint32_t (*Ah)[AW2]    = (uint32_t(*)[AW2])(dsmw);
    uint32_t (*Al)[AW2]    = (uint32_t(*)[AW2])(dsmw + 128 * AW2 * 4);
    uint32_t (*Bp)[8][260] = (uint32_t(*)[8][260])(dsmw + 2 * 128 * AW2 * 4);

    __shared__ float sbg[128];

    const int tid = threadIdx.x;
    const int bm = blockIdx.y * 128;

    const int wid = tid >> 5, lane = tid & 31;
    const int gid = lane >> 2, tg = lane & 3;
    const int wr = wid >> 2, wc = wid & 3;

    if (tid < 128) sbg[tid] = bg[tid];
    __syncthreads();

    #pragma unroll
    for (int it = 0; it < 8; it++) {
        int seg = it * 512 + tid;
        int row = seg >> 5;
        int c4  = (seg & 31) * 4;
        int gr = bm + row;
        float4 d;
        if (gr < M) {
            size_t off = (size_t)gr * HD + c4;
            float4 s  = *(const float4*)&g_S[off];
            float4 ao = *(const float4*)&g_aggO[off];
            float4 ar = *(const float4*)&g_aggR[off];
            float b0 = s.x + sbg[c4]     + ao.x;
            float b1 = s.y + sbg[c4 + 1] + ao.y;
            float b2 = s.z + sbg[c4 + 2] + ao.z;
            float b3 = s.w + sbg[c4 + 3] + ao.w;
            d.x = elu1(b0 + ar.x) - elu1(b0);
            d.y = elu1(b1 + ar.y) - elu1(b1);
            d.z = elu1(b2 + ar.z) - elu1(b2);
            d.w = elu1(b3 + ar.w) - elu1(b3);
        } else d = make_float4(0.f, 0.f, 0.f, 0.f);
        uint32_t h0, l0, h1, l1;
        cvt_splith(d.x, d.y, h0, l0);
        cvt_splith(d.z, d.w, h1, l1);
        int kp = c4 >> 1;
        Ah[row][kp] = h0; Ah[row][kp + 1] = h1;
        Al[row][kp] = l0; Al[row][kp + 1] = l1;
    }
    __syncthreads();

    const int bkp = tid >> 6;
    const int bc4 = (tid & 63) * 4;

    for (int ch = 0; ch < 4; ch++) {
        const int kpoff = (ch >> 1) * 64;
        const int bn    = (ch & 1) * 256;
        uint32_t* C16 = (ch >> 1) ? Q16 : P16;

        uint4 pbh;
        auto loadB = [&](int t) {
            int kpg = kpoff + t * 8 + bkp;
            pbh = *(const uint4*)&g_W1p[kpg * 512 + bn + bc4];
        };
        auto storeB = [&](int buf) {
            *(uint4*)&Bp[buf][bkp][bc4] = pbh;
        };

        float acc[2][8][4];
        #pragma unroll
        for (int i = 0; i < 2; i++)
            #pragma unroll
            for (int j = 0; j < 8; j++)
                #pragma unroll
                for (int r = 0; r < 4; r++) acc[i][j][r] = 0.f;

        loadB(0); storeB(0); __syncthreads();

        for (int t = 0; t < 8; t++) {
            const int cur = t & 1;
            if (t + 1 < 8) loadB(t + 1);

            const int kb = t * 8;
            uint32_t ahf[2][4], alf[2][4];
            #pragma unroll
            for (int mt = 0; mt < 2; mt++) {
                int r0 = wr * 32 + mt * 16 + gid;
                ahf[mt][0] = Ah[r0    ][kb + tg];     alf[mt][0] = Al[r0    ][kb + tg];
                ahf[mt][1] = Ah[r0 + 8][kb + tg];     alf[mt][1] = Al[r0 + 8][kb + tg];
                ahf[mt][2] = Ah[r0    ][kb + tg + 4]; alf[mt][2] = Al[r0    ][kb + tg + 4];
                ahf[mt][3] = Ah[r0 + 8][kb + tg + 4]; alf[mt][3] = Al[r0 + 8][kb + tg + 4];
            }
            #pragma unroll
            for (int nt = 0; nt < 8; nt++) {
                int c = wc * 64 + nt * 8 + gid;
                uint32_t bh[2];
                bh[0] = Bp[cur][tg][c]; bh[1] = Bp[cur][tg + 4][c];
                #pragma unroll
                for (int mt = 0; mt < 2; mt++) {
                    MMA_F16(acc[mt][nt], ahf[mt], bh);
                    MMA_F16(acc[mt][nt], alf[mt], bh);
                }
            }
            if (t + 1 < 8) { storeB(cur ^ 1); __syncthreads(); }
        }

        #pragma unroll
        for (int mt = 0; mt < 2; mt++) {
            int ra = bm + wr * 32 + mt * 16 + gid;
            #pragma unroll
            for (int nt = 0; nt < 8; nt++) {
                int c = bn + wc * 64 + nt * 8 + tg * 2;
                if (ra < M)
                    C16[(size_t)ra * 256 + (c >> 1)] = cvt_h2(acc[mt][nt][0], acc[mt][nt][1]);
                if (ra + 8 < M)
                    C16[(size_t)(ra + 8) * 256 + (c >> 1)] = cvt_h2(acc[mt][nt][2], acc[mt][nt][3]);
            }
        }
        __syncthreads();
    }
}

// =============================================================================
//  gemm23_sel: stage1 single-plane fp16 A; stage2 single-plane fp16 T.
//  smem 96.5KB -> 2 CTAs/SM.
// =============================================================================
#define DSMEM_G23 96512

__global__ void __launch_bounds__(512)
gemm23_sel(const int* __restrict__ esrc, const int* __restrict__ edst,
           const uint32_t* __restrict__ Pm, const uint32_t* __restrict__ Qm,
           const float* __restrict__ br1, const float* __restrict__ br2,
           const float* __restrict__ Wp2, const float* __restrict__ bp2) {
    extern __shared__ char dsm[];
    uint32_t (*Th)[132] = (uint32_t(*)[132])(dsm);                 // 67584 B
    char* s1 = dsm + 67584;
    uint32_t (*Ah)[128][12] = (uint32_t(*)[128][12])(s1);          // 12288 B
    uint32_t (*Bp)[8][260]  = (uint32_t(*)[8][260]) (s1 + 12288);  // 16640 B
    uint32_t (*B2p)[8][132] = (uint32_t(*)[8][132]) (s1);          // reuses stage-1 region

    __shared__ float sW[1280];
    __shared__ float sbc[128];
    __shared__ float sbr1[512];
    __shared__ float sbr2[256];
    __shared__ float red[128][4];
    __shared__ int   smx[NG];

    const int tid = threadIdx.x;
    const int bm = blockIdx.x * 128;
    const int wid = tid >> 5, lane = tid & 31;
    const int gid = lane >> 2, tg = lane & 3;
    const int wr = wid >> 2, wc = wid & 3;

    if (tid < 128) sbc[tid] = g_bc[tid];
    if (tid < 256) sbr2[tid] = br2[tid];
    if (tid < NG)  smx[tid] = (int)0xFF800000;
    sbr1[tid] = br1[tid];
    for (int i = tid; i < 1280; i += 512) sW[i] = Wp2[i];

    // ---------------- stage 1 (K=512, N=256), A single-plane fp16 ----------------
    const int arow = tid >> 2;
    const int akp  = (tid & 3) * 2;
    const int bkp  = tid >> 6;
    const int bc4  = (tid & 63) * 4;

    const int src = __ldg(&esrc[bm + arow]);
    const int dst = __ldg(&edst[bm + arow]);

    uint32_t ah0, ah1;
    uint4 pbh;
    auto loadG1 = [&](int k0) {
        int kp0 = (k0 >> 1) + (tid & 3) * 2;
        uint2 pp = *(const uint2*)&Pm[(size_t)src * 256 + kp0];
        uint2 qq = *(const uint2*)&Qm[(size_t)dst * 256 + kp0];
        float2 p0 = h2f2(pp.x), p1 = h2f2(pp.y);
        float2 q0 = h2f2(qq.x), q1 = h2f2(qq.y);
        int kb = k0 + (tid & 3) * 4;
        float e0 = elu1(p0.x + q0.x + sbr1[kb]);
        float e1 = elu1(p0.y + q0.y + sbr1[kb + 1]);
        float e2 = elu1(p1.x + q1.x + sbr1[kb + 2]);
        float e3 = elu1(p1.y + q1.y + sbr1[kb + 3]);
        ah0 = cvt_h2(e0, e1);
        ah1 = cvt_h2(e2, e3);
        int kpg = (k0 >> 1) + bkp;
        pbh = *(const uint4*)&g_W2p[kpg * 256 + bc4];
    };
    auto storeS1 = [&](int buf) {
        Ah[buf][arow][akp]     = ah0;
        Ah[buf][arow][akp + 1] = ah1;
        *(uint4*)&Bp[buf][bkp][bc4] = pbh;
    };

    float acc[2][8][4];
    #pragma unroll
    for (int i = 0; i < 2; i++)
        #pragma unroll
        for (int j = 0; j < 8; j++)
            #pragma unroll
            for (int r = 0; r < 4; r++) acc[i][j][r] = 0.f;

    loadG1(0); storeS1(0); __syncthreads();

    for (int t = 0; t < 32; t++) {
        const int cur = t & 1;
        if (t + 1 < 32) loadG1((t + 1) << 4);

        uint32_t ahf[2][4];
        #pragma unroll
        for (int mt = 0; mt < 2; mt++) {
            int r0 = wr * 32 + mt * 16 + gid;
            ahf[mt][0] = Ah[cur][r0    ][tg];
            ahf[mt][1] = Ah[cur][r0 + 8][tg];
            ahf[mt][2] = Ah[cur][r0    ][tg + 4];
            ahf[mt][3] = Ah[cur][r0 + 8][tg + 4];
        }
        #pragma unroll
        for (int nt = 0; nt < 8; nt++) {
            int c = wc * 64 + nt * 8 + gid;
            uint32_t bh[2];
            bh[0] = Bp[cur][tg][c]; bh[1] = Bp[cur][tg + 4][c];
            #pragma unroll
            for (int mt = 0; mt < 2; mt++)
                MMA_F16(acc[mt][nt], ahf[mt], bh);
        }
        if (t + 1 < 32) { storeS1(cur ^ 1); __syncthreads(); }
    }

    // pack T = elu(acc + br2) into Th (single fp16 plane)
    #pragma unroll
    for (int mt = 0; mt < 2; mt++) {
        int ra = wr * 32 + mt * 16 + gid, rb = ra + 8;
        #pragma unroll
        for (int nt = 0; nt < 8; nt++) {
            int c = wc * 64 + nt * 8 + tg * 2;
            float e0 = elu1(acc[mt][nt][0] + sbr2[c]);
            float e1 = elu1(acc[mt][nt][1] + sbr2[c + 1]);
            float e2 = elu1(acc[mt][nt][2] + sbr2[c]);
            float e3 = elu1(acc[mt][nt][3] + sbr2[c + 1]);
            Th[ra][c >> 1] = cvt_h2(e0, e1);
            Th[rb][c >> 1] = cvt_h2(e2, e3);
        }
    }
    __syncthreads();   // T complete; stage-1 buffers free

    // ---------------- stage 2 (K=256, N=128), single-plane ----------------
    const int b2kp = tid >> 6;
    const int b2c  = (tid & 63) * 2;

    uint2 qbh;
    auto loadG2 = [&](int s) {
        int kpg = s * 8 + b2kp;
        qbh = *(const uint2*)&g_Wcp[kpg * 128 + b2c];
    };
    auto storeS2 = [&](int buf) {
        *(uint2*)&B2p[buf][b2kp][b2c] = qbh;
    };

    float acc2[2][4][4];
    #pragma unroll
    for (int i = 0; i < 2; i++)
        #pragma unroll
        for (int j = 0; j < 4; j++)
            #pragma unroll
            for (int r = 0; r < 4; r++) acc2[i][j][r] = 0.f;

    loadG2(0); storeS2(0); __syncthreads();

    for (int s = 0; s < 16; s++) {
        const int cur = s & 1;
        if (s + 1 < 16) loadG2(s + 1);

        uint32_t ahf[2][4];
        const int kb = s * 8;
        #pragma unroll
        for (int mt = 0; mt < 2; mt++) {
            int r0 = wr * 32 + mt * 16 + gid;
            ahf[mt][0] = Th[r0    ][kb + tg];
            ahf[mt][1] = Th[r0 + 8][kb + tg];
            ahf[mt][2] = Th[r0    ][kb + tg + 4];
            ahf[mt][3] = Th[r0 + 8][kb + tg + 4];
        }
        #pragma unroll
        for (int nt = 0; nt < 4; nt++) {
            int c = wc * 32 + nt * 8 + gid;
            uint32_t bh[2];
            bh[0] = B2p[cur][tg][c]; bh[1] = B2p[cur][tg + 4][c];
            #pragma unroll
            for (int mt = 0; mt < 2; mt++)
                MMA_F16(acc2[mt][nt], ahf[mt], bh);
        }
        if (s + 1 < 16) { storeS2(cur ^ 1); __syncthreads(); }
    }

    // epilogue: h = elu(acc2 + bc); per-row dot with Wp2[:, lbl]
    #pragma unroll
    for (int mt = 0; mt < 2; mt++) {
        int ra = wr * 32 + mt * 16 + gid, rb = ra + 8;
        int lbla = g_lbl[bm + ra], lblb = g_lbl[bm + rb];
        float pa = 0.f, pb = 0.f;
        #pragma unroll
        for (int nt = 0; nt < 4; nt++) {
            int c = wc * 32 + nt * 8 + tg * 2;
            float h;
            h = elu1(acc2[mt][nt][0] + sbc[c]);     pa += h * sW[c * 10 + lbla];
            h = elu1(acc2[mt][nt][1] + sbc[c + 1]); pa += h * sW[(c + 1) * 10 + lbla];
            h = elu1(acc2[mt][nt][2] + sbc[c]);     pb += h * sW[c * 10 + lblb];
            h = elu1(acc2[mt][nt][3] + sbc[c + 1]); pb += h * sW[(c + 1) * 10 + lblb];
        }
        pa += __shfl_xor_sync(0xffffffffu, pa, 1);
        pa += __shfl_xor_sync(0xffffffffu, pa, 2);
        pb += __shfl_xor_sync(0xffffffffu, pb, 1);
        pb += __shfl_xor_sync(0xffffffffu, pb, 2);
        if (tg == 0) { red[ra][wc] = pa; red[rb][wc] = pb; }
    }
    __syncthreads();
    if (tid < 128) {
        float s = red[tid][0] + red[tid][1] + red[tid][2] + red[tid][3]
                + __ldg(&bp2[g_lbl[bm + tid]]);
        g_sel[bm + tid] = s;
        atomMaxF(&smx[g_seg[bm + tid]], s);
    }
    __syncthreads();
    if (tid < NG) {
        float v = __int_as_float(smx[tid]);
        if (v > -1e37f) atomMaxF(&g_mx[tid], v);
    }
}

// ---------------- edge scatter-add (one red.v4 per edge-lane) --------------------
__global__ void k_scatter(const int* __restrict__ ei) {
    int t = blockIdx.x * blockDim.x + threadIdx.x;
    if (t >= NE * 32) return;
    int e = t >> 5, v = t & 31;
    int s = __ldg(&ei[e]);
    int d = __ldg(&ei[NE + e]);
    float4 m = *(const float4*)&g_Mm[(size_t)s * HD + v * 4];
    float* dst4 = (e < NOCP) ? &g_aggO[(size_t)d * HD + v * 4]
                             : &g_aggR[(size_t)d * HD + v * 4];
    asm volatile("red.global.add.v4.f32 [%0], {%1,%2,%3,%4};"
                 :: "l"(dst4), "f"(m.x), "f"(m.y), "f"(m.z), "f"(m.w) : "memory");
}

// ---------------- segment softmax remainder (exp staged in out) ------------------
__global__ void k_ex(float* __restrict__ out) {
    __shared__ float ss[NG];
    int tid = threadIdx.x;
    if (tid < NG) ss[tid] = 0.f;
    __syncthreads();
    int e = blockIdx.x * blockDim.x + tid;
    if (e < EA) {
        int g = g_seg[e];
        float v = expf(g_sel[e] - __int_as_float(g_mx[g]));
        out[e] = v;
        atomicAdd(&ss[g], v);
    }
    __syncthreads();
    if (tid < NG && ss[tid] != 0.f) atomicAdd(&g_sum[tid], ss[tid]);
}

__global__ void k_probs(float* __restrict__ out) {
    __shared__ unsigned long long sp[NG];
    int tid = threadIdx.x;
    if (tid < NG) sp[tid] = 0ull;
    __syncthreads();
    int e = blockIdx.x * blockDim.x + tid;
    if (e < EA) {
        int g = g_seg[e];
        float p = out[e] / g_sum[g];
        out[e] = p;
        unsigned long long pk =
            ((unsigned long long)__float_as_uint(p) << 32) | (unsigned int)(EA - e);
        atomicMax(&sp[g], pk);
    }
    __syncthreads();
    if (tid < NG && sp[tid] != 0ull) atomicMax(&g_pk[tid], sp[tid]);
}

__global__ void k_tail(float* __restrict__ out) {
    int t = threadIdx.x;
    if (t < NG) {
        unsigned long long pk = g_pk[t];
        out[EA + t]      = __uint_as_float((unsigned int)(pk >> 32));
        out[EA + NG + t] = (float)(EA - (int)(pk & 0xFFFFFFFFu));
    }
}

// ---------------- launch ----------------------------------------------------------
extern "C" void kernel_launch(void* const* d_in, const int* in_sizes, int n_in,
                              void* d_out, int out_size) {
    const int pb = n_in - 13;
    const float* x      = (const float*)d_in[0];
    const int*   ei     = (const int*)  d_in[1];
    const int*   bv     = (const int*)  d_in[2];
    const int*   y      = (const int*)  d_in[3];
    const float* W_self = (const float*)d_in[pb + 0];
    const float* W_nbr  = (const float*)d_in[pb + 1];
    const float* b_gnn  = (const float*)d_in[pb + 2];
    const float* Wr1    = (const float*)d_in[pb + 3];
    const float* br1    = (const float*)d_in[pb + 4];
    const float* Wr2    = (const float*)d_in[pb + 5];
    const float* br2    = (const float*)d_in[pb + 6];
    const float* Wr3    = (const float*)d_in[pb + 7];
    const float* br3    = (const float*)d_in[pb + 8];
    const float* Wp1    = (const float*)d_in[pb + 9];
    const float* bp1    = (const float*)d_in[pb + 10];
    const float* Wp2    = (const float*)d_in[pb + 11];
    const float* bp2    = (const float*)d_in[pb + 12];
    float* out = (float*)d_out;

    void *pS, *pM, *pP, *pQ, *pAR, *pAO;
    cudaGetSymbolAddress(&pS,  g_S);
    cudaGetSymbolAddress(&pM,  g_Mm);
    cudaGetSymbolAddress(&pP,  g_P16);
    cudaGetSymbolAddress(&pQ,  g_Q16);
    cudaGetSymbolAddress(&pAR, g_aggR);
    cudaGetSymbolAddress(&pAO, g_aggO);

    cudaFuncSetAttribute(gemm23_sel,  cudaFuncAttributeMaxDynamicSharedMemorySize, DSMEM_G23);
    cudaFuncSetAttribute(tgemm_wide2, cudaFuncAttributeMaxDynamicSharedMemorySize, DSMEM_WIDE2);

    const int T = 256;

    cudaMemsetAsync(pAR, 0, (size_t)NN * HD * sizeof(float));
    cudaMemsetAsync(pAO, 0, (size_t)NN * HD * sizeof(float));
    k_prep<<<PACK_BLKS + SEG_BLKS, T>>>(Wr2, Wr1, ei, bv, y);
    k_wc  <<<(128 * 128 + T - 1) / T, T>>>(Wr3, br3, Wp1, bp1);

    // node transform GEMMs: S = x@W_self, M = x@W_nbr
    tgemm_sm<<<dim3(1, (NN + 127) / 128, 2), T>>>(x, W_self, W_nbr,
                                                  (float*)pS, (float*)pM, NN);

    k_scatter<<<(NE * 32 + T - 1) / T, T>>>(ei);

    // fused D-computation + P/Q GEMMs
    tgemm_wide2<<<dim3(1, (NN + 127) / 128), 512, DSMEM_WIDE2>>>(
        b_gnn, (uint32_t*)pP, (uint32_t*)pQ, NN);

    // fused GEMM2 + GEMM3 + sel + segment-max
    gemm23_sel<<<EA / 128, 512, DSMEM_G23>>>(
        ei + NOCP, ei + NE + NOCP, (const uint32_t*)pP, (const uint32_t*)pQ,
        br1, br2, Wp2, bp2);

    // segment softmax + fused argmax
    const int segBlocks = (EA + T - 1) / T;
    k_ex   <<<segBlocks, T>>>(out);
    k_probs<<<segBlocks, T>>>(out);
    k_tail <<<1, 64>>>(out);
}